// round 11
// baseline (speedup 1.0000x reference)
#include <cuda_runtime.h>
#include <cuda_bf16.h>
#include <cstdint>

#define BATCH 16
#define PD    31
#define COUT  16

#define A_PLANE 1088                         // 68 x-slots * 16B; plane=(zb*8+yb)
#define A_BYTES (32 * A_PLANE)               // 34816 : 4 zb x 8 yb ring
#define B_BYTES (9 * 2 * 16 * 16 * 2)        // 9216
#define AOFF    0
#define BOFF    A_BYTES                      // 34816
#define REDOFF  (BOFF + B_BYTES)             // 44032 : [8 warp][16 co]
#define SMEM_BYTES (REDOFF + 512)            // 44544 (static, <=48K)

__device__ float g_part[BATCH * PD * COUT];

__device__ __forceinline__ uint32_t smem_u32(const void* p) {
    uint32_t a;
    asm("{ .reg .u64 t; cvta.to.shared.u64 t, %1; cvt.u32.u64 %0, t; }"
        : "=r"(a) : "l"(p));
    return a;
}

__device__ __forceinline__ uint32_t lds32(uint32_t addr) {
    uint32_t v;
    asm volatile("ld.shared.b32 %0, [%1];" : "=r"(v) : "r"(addr));
    return v;
}

__device__ __forceinline__ void ldsm4(uint32_t (&a)[4], uint32_t addr) {
    asm volatile("ldmatrix.sync.aligned.m8n8.x4.shared.b16 {%0,%1,%2,%3}, [%4];"
                 : "=r"(a[0]), "=r"(a[1]), "=r"(a[2]), "=r"(a[3]) : "r"(addr));
}

__device__ __forceinline__ void ldsm2(uint32_t& a0, uint32_t& a1, uint32_t addr) {
    asm volatile("ldmatrix.sync.aligned.m8n8.x2.shared.b16 {%0,%1}, [%2];"
                 : "=r"(a0), "=r"(a1) : "r"(addr));
}

__device__ __forceinline__ void mma16816(float (&d)[4], const uint32_t (&a)[4],
                                         uint32_t b0, uint32_t b1) {
    asm volatile(
        "mma.sync.aligned.m16n8k16.row.col.f32.bf16.bf16.f32 "
        "{%0,%1,%2,%3}, {%4,%5,%6,%7}, {%8,%9}, {%0,%1,%2,%3};"
        : "+f"(d[0]), "+f"(d[1]), "+f"(d[2]), "+f"(d[3])
        : "r"(a[0]), "r"(a[1]), "r"(a[2]), "r"(a[3]), "r"(b0), "r"(b1));
}

__device__ __forceinline__ void mma16808(float (&d)[4], uint32_t a0, uint32_t a1,
                                         uint32_t b0) {
    asm volatile(
        "mma.sync.aligned.m16n8k8.row.col.f32.bf16.bf16.f32 "
        "{%0,%1,%2,%3}, {%4,%5}, {%6}, {%0,%1,%2,%3};"
        : "+f"(d[0]), "+f"(d[1]), "+f"(d[2]), "+f"(d[3])
        : "r"(a0), "r"(a1), "r"(b0));
}

__device__ __forceinline__ uint32_t bfpack(float fhi, float flo) {
    uint32_t r;
    asm("cvt.rn.bf16x2.f32 %0, %1, %2;" : "=r"(r) : "f"(fhi), "f"(flo));
    return r;
}

__global__ __launch_bounds__(256, 2)
void conv_mma_kernel(const float* __restrict__ x, const float* __restrict__ cw,
                     int pz0, int npz) {
    __shared__ __align__(1024) char smem[SMEM_BYTES];
    const uint32_t sbase = smem_u32(smem);
    const int tid  = threadIdx.x;
    const int wid  = tid >> 5;
    const int lane = tid & 31;
    const int b    = blockIdx.x / npz;
    const int pz   = pz0 + (blockIdx.x - b * npz);
    const float* xb = x + (size_t)b * 2097152;

    // ---- B tiles: [win9][kstep2][n16][k16] bf16 ----
    for (int i = tid; i < 4608; i += 256) {
        int k = i & 15, n = (i >> 4) & 15;
        int ks = (i >> 8) & 1, win = i >> 9;
        int dz = win / 3, dy = win % 3;
        int dxl = k >> 3, cin = k & 7, dx = ks * 2 + dxl;
        float w = (dx < 3) ? cw[(((n * 8 + cin) * 3 + dz) * 3 + dy) * 3 + dx] : 0.0f;
        *(__nv_bfloat16*)(smem + BOFF + i * 2) = __float2bfloat16(w);
    }
    // ---- zero x-pad slots (64..67) in all 32 planes ----
    for (int i = tid; i < 32 * 4 * 8; i += 256) {
        int p = i >> 5, xs = (i >> 3) & 3, c = i & 7;
        *(__nv_bfloat16*)(smem + AOFF + p * A_PLANE + (64 + xs) * 16 + c * 2) =
            __float2bfloat16(0.0f);
    }

    const int cp = tid & 3;
    const int xg = tid >> 2;
    auto ldrows = [&](int y0, uint32_t (&pk)[8]) {
#pragma unroll
        for (int j = 0; j < 8; ++j) {
            int zi = j >> 1, yy = j & 1;
            size_t base = ((size_t)((2 * cp) * 64 + (2 * pz + zi)) * 64 + (y0 + yy)) * 64 + xg;
            pk[j] = bfpack(xb[base + 262144], xb[base]);
        }
    };
    auto strows = [&](int y0, const uint32_t (&pk)[8]) {
#pragma unroll
        for (int j = 0; j < 8; ++j) {
            int zi = j >> 1, yy = j & 1;
            int yb = (y0 + yy) & 7;
            *(uint32_t*)(smem + AOFF + (zi * 8 + yb) * A_PLANE + xg * 16 + cp * 4) = pk[j];
        }
    };

    {   // initial rows 0..3 -> ring slots 0..3
        uint32_t pk[8];
        ldrows(0, pk); strows(0, pk);
        ldrows(2, pk); strows(2, pk);
    }
    __syncthreads();

    // interleaved m-rows: rr = lane&15 -> x = wid*8 + (rr>>1), oy = rr&1
    const int par = lane & 1;
    const uint32_t laneAz = sbase + AOFF +
        (uint32_t)((wid * 8 + ((lane & 15) >> 1) + (lane >> 4)) * 16);
    const uint32_t laneB = sbase + BOFF + (lane >> 2) * 32 + (lane & 3) * 4;

    // ---- hoist B: k16 (dx0,1) + k8 (dx2) ----
    uint32_t B16[9][2][2], B8[9][2];
#pragma unroll
    for (int win = 0; win < 9; ++win)
#pragma unroll
        for (int nt = 0; nt < 2; ++nt) {
            uint32_t a0 = laneB + win * 1024 + nt * 256;
            B16[win][nt][0] = lds32(a0);
            B16[win][nt][1] = lds32(a0 + 16);
            B8[win][nt]     = lds32(a0 + 512);
        }

    // px 31 (x=62,63 -> rows 12..15 -> j2/3 of lanes>=16 in warp 7) invalid
    const float mk23 = (wid == 7 && lane >= 16) ? 0.0f : 1.0f;

    float racc[2][4];
#pragma unroll
    for (int nt = 0; nt < 2; ++nt)
#pragma unroll
        for (int j = 0; j < 4; ++j) racc[nt][j] = 0.0f;

    for (int t = 0; t < PD; ++t) {
        uint32_t pk[8];
        const bool pre = (t < PD - 1);
        if (pre) ldrows(2 * t + 4, pk);

        float acc[2][2][4];
#pragma unroll
        for (int oz = 0; oz < 2; ++oz)
#pragma unroll
            for (int nt = 0; nt < 2; ++nt)
#pragma unroll
                for (int j = 0; j < 4; ++j) acc[oz][nt][j] = 0.0f;

#pragma unroll
        for (int dy = 0; dy < 3; ++dy) {
            const uint32_t abase = laneAz + ((2 * t + dy + par) & 7) * A_PLANE;
            uint32_t a16[4][4];
            uint32_t a8[4][2];
#pragma unroll
            for (int zb = 0; zb < 4; ++zb) {
                const uint32_t pb = abase + zb * (8 * A_PLANE);
                ldsm4(a16[zb], pb);
                ldsm2(a8[zb][0], a8[zb][1], pb + 32);
            }
#pragma unroll
            for (int dz = 0; dz < 3; ++dz) {
                const int win = dz * 3 + dy;
#pragma unroll
                for (int nt = 0; nt < 2; ++nt)
#pragma unroll
                    for (int oz = 0; oz < 2; ++oz)
                        mma16816(acc[oz][nt], a16[oz + dz],
                                 B16[win][nt][0], B16[win][nt][1]);
#pragma unroll
                for (int nt = 0; nt < 2; ++nt)
#pragma unroll
                    for (int oz = 0; oz < 2; ++oz)
                        mma16808(acc[oz][nt], a8[oz + dz][0], a8[oz + dz][1],
                                 B8[win][nt]);
            }
        }

        // ---- register-only pooling: oz max, y-pair (xor4), x-pair (xor8) ----
#pragma unroll
        for (int nt = 0; nt < 2; ++nt)
#pragma unroll
            for (int j = 0; j < 4; ++j) {
                float v = fmaxf(acc[0][nt][j], acc[1][nt][j]);
                v = fmaxf(v, __shfl_xor_sync(0xffffffffu, v, 4));
                v = fmaxf(v, __shfl_xor_sync(0xffffffffu, v, 8));
                if (j < 2) racc[nt][j] += v;
                else       racc[nt][j] = fmaf(mk23, v, racc[nt][j]);
            }

        if (pre) strows(2 * t + 4, pk);   // virgin ring slots (disjoint)
        __syncthreads();                  // single barrier per iteration
    }

    // ---- final: sum rows/dups (4x dup -> x0.25), cross-warp via smem ----
    float s[4];
    s[0] = racc[0][0] + racc[0][2];
    s[1] = racc[0][1] + racc[0][3];
    s[2] = racc[1][0] + racc[1][2];
    s[3] = racc[1][1] + racc[1][3];
#pragma unroll
    for (int o = 4; o <= 16; o <<= 1)
#pragma unroll
        for (int q = 0; q < 4; ++q)
            s[q] += __shfl_xor_sync(0xffffffffu, s[q], o);

    float* red = (float*)(smem + REDOFF);
    if (lane < 4) {
        red[wid * 16 + lane * 2 + 0]     = s[0] * 0.25f;
        red[wid * 16 + lane * 2 + 1]     = s[1] * 0.25f;
        red[wid * 16 + 8 + lane * 2 + 0] = s[2] * 0.25f;
        red[wid * 16 + 8 + lane * 2 + 1] = s[3] * 0.25f;
    }
    __syncthreads();
    if (tid < COUT) {
        float S = 0.0f;
#pragma unroll
        for (int w = 0; w < 8; ++w) S += red[w * 16 + tid];
        g_part[(b * PD + pz) * COUT + tid] = S;
    }
}

__global__ void final_kernel(const float* __restrict__ cb,
                             const float* __restrict__ bias,
                             float* __restrict__ out) {
    __shared__ float sacc[256];
    const int t = threadIdx.x;
    const int b = t >> 4, co = t & 15;
    float S = 0.0f;
    for (int pz = 0; pz < PD; ++pz)
        S += g_part[(b * PD + pz) * COUT + co];
    sacc[t] = S * (0.5f / 29791.0f) + 0.5f * cb[co] + bias[co];
    __syncthreads();
    if (co == 0) {
        float s = 0.0f;
#pragma unroll
        for (int k = 0; k < COUT; ++k) s += sacc[b * COUT + k];
        out[b] = s;
    }
}

extern "C" void kernel_launch(void* const* d_in, const int* in_sizes, int n_in,
                              void* d_out, int out_size) {
    (void)in_sizes; (void)n_in; (void)out_size;
    const float* x    = (const float*)d_in[0];
    const float* cw   = (const float*)d_in[1];
    const float* cb   = (const float*)d_in[2];
    const float* bias = (const float*)d_in[3];
    float* out = (float*)d_out;

    conv_mma_kernel<<<BATCH * 16, 256>>>(x, cw, 0, 16);
    conv_mma_kernel<<<BATCH * 15, 256>>>(x, cw, 16, 15);
    final_kernel<<<1, 256>>>(cb, bias, out);
}

// round 12
// speedup vs baseline: 1.0086x; 1.0086x over previous
#include <cuda_runtime.h>
#include <cuda_bf16.h>
#include <cstdint>

#define BATCH 16
#define PD    31
#define COUT  16

#define A_PLANE 1088                         // 68 x-slots * 16B; plane=(zb*8+yb)
#define A_BYTES (32 * A_PLANE)               // 34816 : 4 zb x 8 yb ring
#define B_BYTES (9 * 2 * 16 * 16 * 2)        // 9216
#define AOFF    0
#define BOFF    A_BYTES                      // 34816
#define REDOFF  (BOFF + B_BYTES)             // 44032 : [8 warp][16 co]
#define SMEM_BYTES (REDOFF + 512)            // 44544 (static)

__device__ float g_part[2 * BATCH * PD * COUT];

__device__ __forceinline__ uint32_t smem_u32(const void* p) {
    uint32_t a;
    asm("{ .reg .u64 t; cvta.to.shared.u64 t, %1; cvt.u32.u64 %0, t; }"
        : "=r"(a) : "l"(p));
    return a;
}

__device__ __forceinline__ uint32_t lds32(uint32_t addr) {
    uint32_t v;
    asm volatile("ld.shared.b32 %0, [%1];" : "=r"(v) : "r"(addr));
    return v;
}

__device__ __forceinline__ void ldsm4(uint32_t (&a)[4], uint32_t addr) {
    asm volatile("ldmatrix.sync.aligned.m8n8.x4.shared.b16 {%0,%1,%2,%3}, [%4];"
                 : "=r"(a[0]), "=r"(a[1]), "=r"(a[2]), "=r"(a[3]) : "r"(addr));
}

__device__ __forceinline__ void ldsm2(uint32_t& a0, uint32_t& a1, uint32_t addr) {
    asm volatile("ldmatrix.sync.aligned.m8n8.x2.shared.b16 {%0,%1}, [%2];"
                 : "=r"(a0), "=r"(a1) : "r"(addr));
}

__device__ __forceinline__ void mma16816(float (&d)[4], const uint32_t (&a)[4],
                                         uint32_t b0, uint32_t b1) {
    asm volatile(
        "mma.sync.aligned.m16n8k16.row.col.f32.bf16.bf16.f32 "
        "{%0,%1,%2,%3}, {%4,%5,%6,%7}, {%8,%9}, {%0,%1,%2,%3};"
        : "+f"(d[0]), "+f"(d[1]), "+f"(d[2]), "+f"(d[3])
        : "r"(a[0]), "r"(a[1]), "r"(a[2]), "r"(a[3]), "r"(b0), "r"(b1));
}

__device__ __forceinline__ void mma16808(float (&d)[4], uint32_t a0, uint32_t a1,
                                         uint32_t b0) {
    asm volatile(
        "mma.sync.aligned.m16n8k8.row.col.f32.bf16.bf16.f32 "
        "{%0,%1,%2,%3}, {%4,%5}, {%6}, {%0,%1,%2,%3};"
        : "+f"(d[0]), "+f"(d[1]), "+f"(d[2]), "+f"(d[3])
        : "r"(a0), "r"(a1), "r"(b0));
}

__device__ __forceinline__ uint32_t bfpack(float fhi, float flo) {
    uint32_t r;
    asm("cvt.rn.bf16x2.f32 %0, %1, %2;" : "=r"(r) : "f"(fhi), "f"(flo));
    return r;
}

__global__ __launch_bounds__(256, 2)
void conv_mma_kernel(const float* __restrict__ x, const float* __restrict__ cw) {
    __shared__ __align__(1024) char smem[SMEM_BYTES];
    const uint32_t sbase = smem_u32(smem);
    const int tid  = threadIdx.x;
    const int wid  = tid >> 5;
    const int lane = tid & 31;
    // grid: [(b*PD+pz)*2 + th]
    const int th   = blockIdx.x & 1;
    const int bp   = blockIdx.x >> 1;
    const int b    = bp / PD;
    const int pz   = bp - b * PD;
    const int t0   = th ? 16 : 0;
    const int t1   = th ? PD : 16;
    const float* xb = x + (size_t)b * 2097152;

    // ---- B tiles: [win9][kstep2][n16][k16] bf16 ----
    for (int i = tid; i < 4608; i += 256) {
        int k = i & 15, n = (i >> 4) & 15;
        int ks = (i >> 8) & 1, win = i >> 9;
        int dz = win / 3, dy = win % 3;
        int dxl = k >> 3, cin = k & 7, dx = ks * 2 + dxl;
        float w = (dx < 3) ? cw[(((n * 8 + cin) * 3 + dz) * 3 + dy) * 3 + dx] : 0.0f;
        *(__nv_bfloat16*)(smem + BOFF + i * 2) = __float2bfloat16(w);
    }
    // ---- zero x-pad slots (64..67) in all 32 planes ----
    for (int i = tid; i < 32 * 4 * 8; i += 256) {
        int p = i >> 5, xs = (i >> 3) & 3, c = i & 7;
        *(__nv_bfloat16*)(smem + AOFF + p * A_PLANE + (64 + xs) * 16 + c * 2) =
            __float2bfloat16(0.0f);
    }

    const int cp = tid & 3;
    const int xg = tid >> 2;
    auto ldrows = [&](int y0, uint32_t (&pk)[8]) {
#pragma unroll
        for (int j = 0; j < 8; ++j) {
            int zi = j >> 1, yy = j & 1;
            size_t base = ((size_t)((2 * cp) * 64 + (2 * pz + zi)) * 64 + (y0 + yy)) * 64 + xg;
            pk[j] = bfpack(xb[base + 262144], xb[base]);
        }
    };
    auto strows = [&](int y0, const uint32_t (&pk)[8]) {
#pragma unroll
        for (int j = 0; j < 8; ++j) {
            int zi = j >> 1, yy = j & 1;
            int yb = (y0 + yy) & 7;
            *(uint32_t*)(smem + AOFF + (zi * 8 + yb) * A_PLANE + xg * 16 + cp * 4) = pk[j];
        }
    };

    {   // prologue: rows 2*t0 .. 2*t0+3
        uint32_t pk[8];
        ldrows(2 * t0, pk);     strows(2 * t0, pk);
        ldrows(2 * t0 + 2, pk); strows(2 * t0 + 2, pk);
    }
    __syncthreads();

    // interleaved m-rows: rr = lane&15 -> x = wid*8 + (rr>>1), oy = rr&1
    const int par = lane & 1;
    const uint32_t laneAz = sbase + AOFF +
        (uint32_t)((wid * 8 + ((lane & 15) >> 1) + (lane >> 4)) * 16);
    const uint32_t laneB = sbase + BOFF + (lane >> 2) * 32 + (lane & 3) * 4;

    // ---- hoist B: k16 (dx0,1) + k8 (dx2) ----
    uint32_t B16[9][2][2], B8[9][2];
#pragma unroll
    for (int win = 0; win < 9; ++win)
#pragma unroll
        for (int nt = 0; nt < 2; ++nt) {
            uint32_t a0 = laneB + win * 1024 + nt * 256;
            B16[win][nt][0] = lds32(a0);
            B16[win][nt][1] = lds32(a0 + 16);
            B8[win][nt]     = lds32(a0 + 512);
        }

    // px 31 (x=62,63 -> j2/3 of lanes>=16 in warp 7) invalid
    const float mk23 = (wid == 7 && lane >= 16) ? 0.0f : 1.0f;

    float racc[2][4];
#pragma unroll
    for (int nt = 0; nt < 2; ++nt)
#pragma unroll
        for (int j = 0; j < 4; ++j) racc[nt][j] = 0.0f;

    for (int t = t0; t < t1; ++t) {
        uint32_t pk[8];
        const bool pre = (t + 1 < t1);
        if (pre) ldrows(2 * t + 4, pk);

        float acc[2][2][4];
#pragma unroll
        for (int oz = 0; oz < 2; ++oz)
#pragma unroll
            for (int nt = 0; nt < 2; ++nt)
#pragma unroll
                for (int j = 0; j < 4; ++j) acc[oz][nt][j] = 0.0f;

#pragma unroll
        for (int dy = 0; dy < 3; ++dy) {
            const uint32_t abase = laneAz + ((2 * t + dy + par) & 7) * A_PLANE;
            uint32_t a16[4][4];
            uint32_t a8[4][2];
#pragma unroll
            for (int zb = 0; zb < 4; ++zb) {
                const uint32_t pb = abase + zb * (8 * A_PLANE);
                ldsm4(a16[zb], pb);
                ldsm2(a8[zb][0], a8[zb][1], pb + 32);
            }
#pragma unroll
            for (int dz = 0; dz < 3; ++dz) {
                const int win = dz * 3 + dy;
#pragma unroll
                for (int nt = 0; nt < 2; ++nt)
#pragma unroll
                    for (int oz = 0; oz < 2; ++oz)
                        mma16816(acc[oz][nt], a16[oz + dz],
                                 B16[win][nt][0], B16[win][nt][1]);
#pragma unroll
                for (int nt = 0; nt < 2; ++nt)
#pragma unroll
                    for (int oz = 0; oz < 2; ++oz)
                        mma16808(acc[oz][nt], a8[oz + dz][0], a8[oz + dz][1],
                                 B8[win][nt]);
            }
        }

        // ---- register-only pooling: oz max, y-pair (xor4), x-pair (xor8) ----
#pragma unroll
        for (int nt = 0; nt < 2; ++nt)
#pragma unroll
            for (int j = 0; j < 4; ++j) {
                float v = fmaxf(acc[0][nt][j], acc[1][nt][j]);
                v = fmaxf(v, __shfl_xor_sync(0xffffffffu, v, 4));
                v = fmaxf(v, __shfl_xor_sync(0xffffffffu, v, 8));
                if (j < 2) racc[nt][j] += v;
                else       racc[nt][j] = fmaf(mk23, v, racc[nt][j]);
            }

        if (pre) strows(2 * t + 4, pk);   // virgin ring slots (disjoint)
        __syncthreads();                  // single barrier per iteration
    }

    // ---- final: sum rows/dups (4x dup -> x0.25), cross-warp via smem ----
    float s[4];
    s[0] = racc[0][0] + racc[0][2];
    s[1] = racc[0][1] + racc[0][3];
    s[2] = racc[1][0] + racc[1][2];
    s[3] = racc[1][1] + racc[1][3];
#pragma unroll
    for (int o = 4; o <= 16; o <<= 1)
#pragma unroll
        for (int q = 0; q < 4; ++q)
            s[q] += __shfl_xor_sync(0xffffffffu, s[q], o);

    float* red = (float*)(smem + REDOFF);
    if (lane < 4) {
        red[wid * 16 + lane * 2 + 0]     = s[0] * 0.25f;
        red[wid * 16 + lane * 2 + 1]     = s[1] * 0.25f;
        red[wid * 16 + 8 + lane * 2 + 0] = s[2] * 0.25f;
        red[wid * 16 + 8 + lane * 2 + 1] = s[3] * 0.25f;
    }
    __syncthreads();
    if (tid < COUT) {
        float S = 0.0f;
#pragma unroll
        for (int w = 0; w < 8; ++w) S += red[w * 16 + tid];
        g_part[((th * BATCH + b) * PD + pz) * COUT + tid] = S;
    }
}

__global__ void final_kernel(const float* __restrict__ cb,
                             const float* __restrict__ bias,
                             float* __restrict__ out) {
    __shared__ float sacc[256];
    const int t = threadIdx.x;
    const int b = t >> 4, co = t & 15;
    float S = 0.0f;
#pragma unroll
    for (int h = 0; h < 2; ++h)
        for (int pz = 0; pz < PD; ++pz)
            S += g_part[((h * BATCH + b) * PD + pz) * COUT + co];
    sacc[t] = S * (0.5f / 29791.0f) + 0.5f * cb[co] + bias[co];
    __syncthreads();
    if (co == 0) {
        float s = 0.0f;
#pragma unroll
        for (int k = 0; k < COUT; ++k) s += sacc[b * COUT + k];
        out[b] = s;
    }
}

extern "C" void kernel_launch(void* const* d_in, const int* in_sizes, int n_in,
                              void* d_out, int out_size) {
    (void)in_sizes; (void)n_in; (void)out_size;
    const float* x    = (const float*)d_in[0];
    const float* cw   = (const float*)d_in[1];
    const float* cb   = (const float*)d_in[2];
    const float* bias = (const float*)d_in[3];
    float* out = (float*)d_out;

    conv_mma_kernel<<<2 * BATCH * PD, 256>>>(x, cw);
    final_kernel<<<1, 256>>>(cb, bias, out);
}

// round 13
// speedup vs baseline: 1.0643x; 1.0552x over previous
#include <cuda_runtime.h>
#include <cuda_bf16.h>
#include <cstdint>

#define BATCH 16
#define PD    31
#define COUT  16

#define A_PLANE 1088                         // 68 x-slots * 16B; plane=(zb*8+yb)
#define A_BYTES (32 * A_PLANE)               // 34816 : 4 zb x 8 yb ring
#define B_BYTES (9 * 2 * 16 * 16 * 2)        // 9216
#define AOFF    0
#define BOFF    A_BYTES                      // 34816
#define REDOFF  (BOFF + B_BYTES)             // 44032 : [8 warp][16 co]
#define SMEM_BYTES (REDOFF + 512)            // 44544 (static)

__device__ float g_part[BATCH * PD * COUT];

__device__ __forceinline__ uint32_t smem_u32(const void* p) {
    uint32_t a;
    asm("{ .reg .u64 t; cvta.to.shared.u64 t, %1; cvt.u32.u64 %0, t; }"
        : "=r"(a) : "l"(p));
    return a;
}

__device__ __forceinline__ uint32_t lds32(uint32_t addr) {
    uint32_t v;
    asm volatile("ld.shared.b32 %0, [%1];" : "=r"(v) : "r"(addr));
    return v;
}

__device__ __forceinline__ void ldsm4(uint32_t (&a)[4], uint32_t addr) {
    asm volatile("ldmatrix.sync.aligned.m8n8.x4.shared.b16 {%0,%1,%2,%3}, [%4];"
                 : "=r"(a[0]), "=r"(a[1]), "=r"(a[2]), "=r"(a[3]) : "r"(addr));
}

__device__ __forceinline__ void mma16816(float (&d)[4], const uint32_t (&a)[4],
                                         uint32_t b0, uint32_t b1) {
    asm volatile(
        "mma.sync.aligned.m16n8k16.row.col.f32.bf16.bf16.f32 "
        "{%0,%1,%2,%3}, {%4,%5,%6,%7}, {%8,%9}, {%0,%1,%2,%3};"
        : "+f"(d[0]), "+f"(d[1]), "+f"(d[2]), "+f"(d[3])
        : "r"(a[0]), "r"(a[1]), "r"(a[2]), "r"(a[3]), "r"(b0), "r"(b1));
}

__device__ __forceinline__ void mma16816s(float (&d)[4], uint32_t a0, uint32_t a1,
                                          uint32_t a2, uint32_t a3,
                                          uint32_t b0, uint32_t b1) {
    asm volatile(
        "mma.sync.aligned.m16n8k16.row.col.f32.bf16.bf16.f32 "
        "{%0,%1,%2,%3}, {%4,%5,%6,%7}, {%8,%9}, {%0,%1,%2,%3};"
        : "+f"(d[0]), "+f"(d[1]), "+f"(d[2]), "+f"(d[3])
        : "r"(a0), "r"(a1), "r"(a2), "r"(a3), "r"(b0), "r"(b1));
}

__device__ __forceinline__ void mma16808(float (&d)[4], uint32_t a0, uint32_t a1,
                                         uint32_t b0) {
    asm volatile(
        "mma.sync.aligned.m16n8k8.row.col.f32.bf16.bf16.f32 "
        "{%0,%1,%2,%3}, {%4,%5}, {%6}, {%0,%1,%2,%3};"
        : "+f"(d[0]), "+f"(d[1]), "+f"(d[2]), "+f"(d[3])
        : "r"(a0), "r"(a1), "r"(b0));
}

__device__ __forceinline__ uint32_t bfpack(float fhi, float flo) {
    uint32_t r;
    asm("cvt.rn.bf16x2.f32 %0, %1, %2;" : "=r"(r) : "f"(fhi), "f"(flo));
    return r;
}

__global__ __launch_bounds__(256, 2)
void conv_mma_kernel(const float* __restrict__ x, const float* __restrict__ cw,
                     int pz0, int npz) {
    __shared__ __align__(1024) char smem[SMEM_BYTES];
    const uint32_t sbase = smem_u32(smem);
    const int tid  = threadIdx.x;
    const int wid  = tid >> 5;
    const int lane = tid & 31;
    const int b    = blockIdx.x / npz;
    const int pz   = pz0 + (blockIdx.x - b * npz);
    const float* xb = x + (size_t)b * 2097152;

    // ---- B tiles: [win9][kstep2][n16][k16] bf16 ----
    for (int i = tid; i < 4608; i += 256) {
        int k = i & 15, n = (i >> 4) & 15;
        int ks = (i >> 8) & 1, win = i >> 9;
        int dz = win / 3, dy = win % 3;
        int dxl = k >> 3, cin = k & 7, dx = ks * 2 + dxl;
        float w = (dx < 3) ? cw[(((n * 8 + cin) * 3 + dz) * 3 + dy) * 3 + dx] : 0.0f;
        *(__nv_bfloat16*)(smem + BOFF + i * 2) = __float2bfloat16(w);
    }
    // ---- zero x-pad slots (64..67) in all 32 planes ----
    for (int i = tid; i < 32 * 4 * 8; i += 256) {
        int p = i >> 5, xs = (i >> 3) & 3, c = i & 7;
        *(__nv_bfloat16*)(smem + AOFF + p * A_PLANE + (64 + xs) * 16 + c * 2) =
            __float2bfloat16(0.0f);
    }

    const int cp = tid & 3;
    const int xg = tid >> 2;
    auto ldrows = [&](int y0, uint32_t (&pk)[8]) {
#pragma unroll
        for (int j = 0; j < 8; ++j) {
            int zi = j >> 1, yy = j & 1;
            size_t base = ((size_t)((2 * cp) * 64 + (2 * pz + zi)) * 64 + (y0 + yy)) * 64 + xg;
            pk[j] = bfpack(xb[base + 262144], xb[base]);
        }
    };
    auto strows = [&](int y0, const uint32_t (&pk)[8]) {
#pragma unroll
        for (int j = 0; j < 8; ++j) {
            int zi = j >> 1, yy = j & 1;
            int yb = (y0 + yy) & 7;
            *(uint32_t*)(smem + AOFF + (zi * 8 + yb) * A_PLANE + xg * 16 + cp * 4) = pk[j];
        }
    };

    {   // initial rows 0..3 -> ring slots 0..3
        uint32_t pk[8];
        ldrows(0, pk); strows(0, pk);
        ldrows(2, pk); strows(2, pk);
    }
    __syncthreads();

    // interleaved m-rows: rr = lane&15 -> x = wid*8 + (rr>>1), oy = rr&1
    const int par = lane & 1;
    const uint32_t xterm = (uint32_t)((wid * 8 + ((lane & 15) >> 1)) * 16);
    // a16 base: kh = lane>>4 selects k-half (dx0/dx1 16B apart)
    const uint32_t laneAz = sbase + AOFF + xterm + (lane >> 4) * 16;
    // a8-pair base: +32 (dx2); lanes 16-31 address next zb plane
    const uint32_t laneA8 = sbase + AOFF + xterm + 32 + (lane >> 4) * (8 * A_PLANE);
    const uint32_t laneB  = sbase + BOFF + (lane >> 2) * 32 + (lane & 3) * 4;

    // ---- hoist B: k16 (dx0,1) + k8 (dx2) ----
    uint32_t B16[9][2][2], B8[9][2];
#pragma unroll
    for (int win = 0; win < 9; ++win)
#pragma unroll
        for (int nt = 0; nt < 2; ++nt) {
            uint32_t a0 = laneB + win * 1024 + nt * 256;
            B16[win][nt][0] = lds32(a0);
            B16[win][nt][1] = lds32(a0 + 16);
            B8[win][nt]     = lds32(a0 + 512);
        }

    // px 31 (x=62,63 -> j2/3 of lanes>=16 in warp 7) invalid
    const float mk23 = (wid == 7 && lane >= 16) ? 0.0f : 1.0f;

    float racc[2][4];
#pragma unroll
    for (int nt = 0; nt < 2; ++nt)
#pragma unroll
        for (int j = 0; j < 4; ++j) racc[nt][j] = 0.0f;

    for (int t = 0; t < PD; ++t) {
        uint32_t pk[8];
        const bool pre = (t < PD - 1);
        if (pre) ldrows(2 * t + 4, pk);

        float acc[2][2][4];
#pragma unroll
        for (int oz = 0; oz < 2; ++oz)
#pragma unroll
            for (int nt = 0; nt < 2; ++nt)
#pragma unroll
                for (int j = 0; j < 4; ++j) acc[oz][nt][j] = 0.0f;

#pragma unroll
        for (int dy = 0; dy < 3; ++dy) {
            const uint32_t ybo = ((2 * t + dy + par) & 7) * A_PLANE;
            uint32_t a16[4][4];
            uint32_t a8p[2][4];            // [pair zb{0,1} | zb{2,3}]
#pragma unroll
            for (int zb = 0; zb < 4; ++zb)
                ldsm4(a16[zb], laneAz + ybo + zb * (8 * A_PLANE));
            ldsm4(a8p[0], laneA8 + ybo);                       // zb 0,1
            ldsm4(a8p[1], laneA8 + ybo + 2 * (8 * A_PLANE));   // zb 2,3

#pragma unroll
            for (int dz = 0; dz < 3; ++dz) {
                const int win = dz * 3 + dy;
#pragma unroll
                for (int nt = 0; nt < 2; ++nt)
#pragma unroll
                    for (int oz = 0; oz < 2; ++oz)
                        mma16816(acc[oz][nt], a16[oz + dz],
                                 B16[win][nt][0], B16[win][nt][1]);
            }
            // dx2, dz{0,1} folded into k16: B = {B8[dy], B8[3+dy]}
#pragma unroll
            for (int nt = 0; nt < 2; ++nt) {
                mma16816s(acc[0][nt], a8p[0][0], a8p[0][1], a8p[0][2], a8p[0][3],
                          B8[dy][nt], B8[3 + dy][nt]);
                mma16816s(acc[1][nt], a8p[0][2], a8p[0][3], a8p[1][0], a8p[1][1],
                          B8[dy][nt], B8[3 + dy][nt]);
            }
            // dx2, dz=2 as k8
#pragma unroll
            for (int nt = 0; nt < 2; ++nt) {
                mma16808(acc[0][nt], a8p[1][0], a8p[1][1], B8[6 + dy][nt]);
                mma16808(acc[1][nt], a8p[1][2], a8p[1][3], B8[6 + dy][nt]);
            }
        }

        // ---- register-only pooling: oz max, y-pair (xor4), x-pair (xor8) ----
#pragma unroll
        for (int nt = 0; nt < 2; ++nt)
#pragma unroll
            for (int j = 0; j < 4; ++j) {
                float v = fmaxf(acc[0][nt][j], acc[1][nt][j]);
                v = fmaxf(v, __shfl_xor_sync(0xffffffffu, v, 4));
                v = fmaxf(v, __shfl_xor_sync(0xffffffffu, v, 8));
                if (j < 2) racc[nt][j] += v;
                else       racc[nt][j] = fmaf(mk23, v, racc[nt][j]);
            }

        if (pre) strows(2 * t + 4, pk);   // virgin ring slots (disjoint)
        __syncthreads();                  // single barrier per iteration
    }

    // ---- final: sum rows/dups (4x dup -> x0.25), cross-warp via smem ----
    float s[4];
    s[0] = racc[0][0] + racc[0][2];
    s[1] = racc[0][1] + racc[0][3];
    s[2] = racc[1][0] + racc[1][2];
    s[3] = racc[1][1] + racc[1][3];
#pragma unroll
    for (int o = 4; o <= 16; o <<= 1)
#pragma unroll
        for (int q = 0; q < 4; ++q)
            s[q] += __shfl_xor_sync(0xffffffffu, s[q], o);

    float* red = (float*)(smem + REDOFF);
    if (lane < 4) {
        red[wid * 16 + lane * 2 + 0]     = s[0] * 0.25f;
        red[wid * 16 + lane * 2 + 1]     = s[1] * 0.25f;
        red[wid * 16 + 8 + lane * 2 + 0] = s[2] * 0.25f;
        red[wid * 16 + 8 + lane * 2 + 1] = s[3] * 0.25f;
    }
    __syncthreads();
    if (tid < COUT) {
        float S = 0.0f;
#pragma unroll
        for (int w = 0; w < 8; ++w) S += red[w * 16 + tid];
        g_part[(b * PD + pz) * COUT + tid] = S;
    }
}

__global__ void final_kernel(const float* __restrict__ cb,
                             const float* __restrict__ bias,
                             float* __restrict__ out) {
    __shared__ float sacc[256];
    const int t = threadIdx.x;
    const int b = t >> 4, co = t & 15;
    float S = 0.0f;
    for (int pz = 0; pz < PD; ++pz)
        S += g_part[(b * PD + pz) * COUT + co];
    sacc[t] = S * (0.5f / 29791.0f) + 0.5f * cb[co] + bias[co];
    __syncthreads();
    if (co == 0) {
        float s = 0.0f;
#pragma unroll
        for (int k = 0; k < COUT; ++k) s += sacc[b * COUT + k];
        out[b] = s;
    }
}

extern "C" void kernel_launch(void* const* d_in, const int* in_sizes, int n_in,
                              void* d_out, int out_size) {
    (void)in_sizes; (void)n_in; (void)out_size;
    const float* x    = (const float*)d_in[0];
    const float* cw   = (const float*)d_in[1];
    const float* cb   = (const float*)d_in[2];
    const float* bias = (const float*)d_in[3];
    float* out = (float*)d_out;

    // 3-node graph (ncu samples conv); pz-split across two launches
    conv_mma_kernel<<<BATCH * 16, 256>>>(x, cw, 0, 16);
    conv_mma_kernel<<<BATCH * 15, 256>>>(x, cw, 16, 15);
    final_kernel<<<1, 256>>>(cb, bias, out);
}